// round 4
// baseline (speedup 1.0000x reference)
#include <cuda_runtime.h>

#define TB   64      // batch
#define TT   512     // timesteps
#define DIN  64
#define DM   512     // d_model
#define DOUT 64
#define NCB  16      // column blocks
#define NC   32      // cols per CTA
#define NBB  8       // batch blocks
#define NB   8       // batches per CTA
#define GB   128     // persistent grid

typedef unsigned long long u64;

// ---- device scratch (allocation-free) --------------------------------------
__device__ float g_pre0 [TT * TB * DM];   // [t][b][j]
__device__ float g_h1all[TT * TB * DM];   // [t][b][j]
__device__ float g_h0   [2 * TB * DM];    // ping-pong h0
__device__ float g_h1   [2 * TB * DM];    // ping-pong h1
__device__ unsigned int g_bars[NBB];

// packed fp32x2 FMA (Blackwell FFMA2; only reachable via PTX)
__device__ __forceinline__ u64 ffma2(u64 a, u64 b, u64 c) {
    u64 d;
    asm("fma.rn.f32x2 %0, %1, %2, %3;" : "=l"(d) : "l"(a), "l"(b), "l"(c));
    return d;
}
__device__ __forceinline__ float f2sum(u64 v) {
    float x, y;
    asm("mov.b64 {%0,%1}, %2;" : "=f"(x), "=f"(y) : "l"(v));
    return x + y;
}

// ---------------------------------------------------------------------------
// k_pre: pre0[t][b][:] = x[b][t][:] @ Wih0 + (bih0+bhh0). grid 512, 256 thr.
// Wp[k2][j] = (W[2k2][j], W[2k2+1][j]) pairs; 8-batch register tiles.
// Also resets barrier counters and zeros parity-1 hidden state.
// ---------------------------------------------------------------------------
__global__ void __launch_bounds__(256, 1)
k_pre(const float* __restrict__ data, const float* __restrict__ Wih0,
      const float* __restrict__ bih0, const float* __restrict__ bhh0)
{
    extern __shared__ float sm[];
    float*  xs = sm;                  // [64][64]
    float2* Wp = (float2*)(sm + TB * DIN);   // [32 k2][512 j]
    float*  bs = sm + TB * DIN + 2 * 32 * DM; // [512]

    const int t = blockIdx.x, tid = threadIdx.x;
    if (t == 0 && tid < NBB) g_bars[tid] = 0u;
    if (t < 128) {
        int i = t * 256 + tid;
        g_h0[TB * DM + i] = 0.0f;
        g_h1[TB * DM + i] = 0.0f;
    }

    for (int i = tid; i < TB * DIN; i += 256) {
        int b = i >> 6, k = i & 63;
        xs[b * DIN + k] = data[(b * TT + t) * DIN + k];
    }
    for (int i = tid; i < 32 * DM; i += 256) {
        int k2 = i >> 9, j = i & 511;
        Wp[i] = make_float2(Wih0[(2 * k2) * DM + j], Wih0[(2 * k2 + 1) * DM + j]);
    }
    for (int i = tid; i < DM; i += 256) bs[i] = bih0[i] + bhh0[i];
    __syncthreads();

    const int j0 = tid;          // cols j0 and j0+256
    for (int g = 0; g < 8; g++) {            // 8 batches per group
        u64 acc[2][8];
        #pragma unroll
        for (int c = 0; c < 2; c++)
            #pragma unroll
            for (int b = 0; b < 8; b++) acc[c][b] = 0ULL;
        #pragma unroll 8
        for (int k2 = 0; k2 < 32; k2++) {
            u64 w0 = *(const u64*)&Wp[k2 * DM + j0];
            u64 w1 = *(const u64*)&Wp[k2 * DM + j0 + 256];
            #pragma unroll
            for (int b = 0; b < 8; b++) {
                u64 h = *(const u64*)&xs[(g * 8 + b) * DIN + 2 * k2]; // broadcast
                acc[0][b] = ffma2(h, w0, acc[0][b]);
                acc[1][b] = ffma2(h, w1, acc[1][b]);
            }
        }
        #pragma unroll
        for (int b = 0; b < 8; b++) {
            int bg = g * 8 + b;
            g_pre0[(t * TB + bg) * DM + j0]       = f2sum(acc[0][b]) + bs[j0];
            g_pre0[(t * TB + bg) * DM + j0 + 256] = f2sum(acc[1][b]) + bs[j0 + 256];
        }
    }
}

// ---------------------------------------------------------------------------
// per-batchblock grid barrier (16 col-block CTAs; all 128 CTAs co-resident)
// ---------------------------------------------------------------------------
__device__ __forceinline__ void gsync(int bb, unsigned int* tgt)
{
    *tgt += NCB;
    __threadfence();
    __syncthreads();
    if (threadIdx.x == 0) {
        atomicAdd(&g_bars[bb], 1u);
        while (*(volatile unsigned int*)&g_bars[bb] < *tgt) { }
    }
    __syncthreads();
}

__device__ __forceinline__ void stage(float* dst, const float* src, int tid)
{
    const float4* s = (const float4*)src;
    float4*       d = (float4*)dst;
    #pragma unroll
    for (int j = 0; j < 4; j++) d[tid + 256 * j] = __ldcg(&s[tid + 256 * j]);
}

// ---------------------------------------------------------------------------
// k_seq: 512 sequential steps, 128 persistent CTAs x 256 thr, smem 229504 B.
// CTA (bb,cb): batches [8bb,8bb+8) x cols [32cb,32cb+32). Weights SMEM-resident
// interleaved float4 along k. Split-k across 8 warps; FFMA2 inner loops.
// h0s survives across steps (phase-2 stage feeds next phase-1).
// ---------------------------------------------------------------------------
__global__ void __launch_bounds__(256, 1)
k_seq(const float* __restrict__ Whh0, const float* __restrict__ Wih1,
      const float* __restrict__ bih1, const float* __restrict__ Whh1,
      const float* __restrict__ bhh1)
{
    extern __shared__ float sm[];
    float4* W0  = (float4*)sm;          // [4096] float4 (Whh0 slice)
    float4* W1  = W0 + 4096;
    float4* W2  = W1 + 4096;
    float*  h0s = sm + 3 * 16384;       // [8][512]  (persists across steps)
    float*  h1s = h0s + NB * DM;        // [8][512]  (also reduction buffer)
    float*  b1s = h1s + NB * DM;        // [32]

    const int tid = threadIdx.x;
    const int cb  = blockIdx.x & (NCB - 1);
    const int bb  = blockIdx.x >> 4;
    const int c0  = cb * NC, b0 = bb * NB;

    for (int idx = tid; idx < 4096; idx += 256) {
        int kg = idx >> 5, c = idx & 31;
        int kb = kg * 4, cg = c0 + c;
        float4 v;
        v.x = Whh0[(kb+0)*DM+cg]; v.y = Whh0[(kb+1)*DM+cg];
        v.z = Whh0[(kb+2)*DM+cg]; v.w = Whh0[(kb+3)*DM+cg];
        W0[idx] = v;
        v.x = Wih1[(kb+0)*DM+cg]; v.y = Wih1[(kb+1)*DM+cg];
        v.z = Wih1[(kb+2)*DM+cg]; v.w = Wih1[(kb+3)*DM+cg];
        W1[idx] = v;
        v.x = Whh1[(kb+0)*DM+cg]; v.y = Whh1[(kb+1)*DM+cg];
        v.z = Whh1[(kb+2)*DM+cg]; v.w = Whh1[(kb+3)*DM+cg];
        W2[idx] = v;
    }
    if (tid < NC) b1s[tid] = bih1[c0 + tid] + bhh1[c0 + tid];

    // prime h0s with zeros (parity-1 buffer, zeroed by k_pre)
    stage(h0s, g_h0 + TB * DM + b0 * DM, tid);
    __syncthreads();

    const int w   = tid >> 5;     // warp = k-slice; also batch id in reduction
    const int lc  = tid & 31;
    const int kg0 = w * 16;
    const ulonglong2* W0v = (const ulonglong2*)W0;
    const ulonglong2* W1v = (const ulonglong2*)W1;
    const ulonglong2* W2v = (const ulonglong2*)W2;
    unsigned int tgt = 0;
    u64 acc[8];

    for (int t = 0; t < TT; t++) {
        const int p = t & 1, rp = p ^ 1;
        float pre = __ldg(&g_pre0[(t * TB + b0 + w) * DM + c0 + lc]);

        // ===== phase 1: h0_new = tanh(pre + h0_prev @ Whh0) =====
        #pragma unroll
        for (int b = 0; b < 8; b++) acc[b] = 0ULL;
        #pragma unroll 4
        for (int kg = kg0; kg < kg0 + 16; kg++) {
            ulonglong2 wv = W0v[kg * 32 + lc];
            #pragma unroll
            for (int b = 0; b < 8; b++) {
                ulonglong2 h = *(const ulonglong2*)&h0s[b * DM + kg * 4];
                acc[b] = ffma2(h.x, wv.x, acc[b]);
                acc[b] = ffma2(h.y, wv.y, acc[b]);
            }
        }
        #pragma unroll
        for (int b = 0; b < 8; b++) h1s[(w * 8 + b) * 32 + lc] = f2sum(acc[b]);
        __syncthreads();
        {
            float s = pre;
            #pragma unroll
            for (int r = 0; r < 8; r++) s += h1s[(r * 8 + w) * 32 + lc];
            g_h0[p * TB * DM + (b0 + w) * DM + c0 + lc] = tanhf(s);
        }
        gsync(bb, &tgt);    // h0_new visible across col-blocks

        // stage h0_new (persists into next step) + h1_prev
        stage(h0s, g_h0 + p  * TB * DM + b0 * DM, tid);
        stage(h1s, g_h1 + rp * TB * DM + b0 * DM, tid);
        __syncthreads();

        // ===== phase 2: h1_new = tanh(b1 + h0_new@Wih1 + h1_prev@Whh1) =====
        #pragma unroll
        for (int b = 0; b < 8; b++) acc[b] = 0ULL;
        #pragma unroll 2
        for (int kg = kg0; kg < kg0 + 16; kg++) {
            ulonglong2 u1 = W1v[kg * 32 + lc];
            ulonglong2 u2 = W2v[kg * 32 + lc];
            #pragma unroll
            for (int b = 0; b < 8; b++) {
                ulonglong2 a = *(const ulonglong2*)&h0s[b * DM + kg * 4];
                ulonglong2 c = *(const ulonglong2*)&h1s[b * DM + kg * 4];
                acc[b] = ffma2(a.x, u1.x, acc[b]);
                acc[b] = ffma2(a.y, u1.y, acc[b]);
                acc[b] = ffma2(c.x, u2.x, acc[b]);
                acc[b] = ffma2(c.y, u2.y, acc[b]);
            }
        }
        __syncthreads();    // all warps done reading h1s
        #pragma unroll
        for (int b = 0; b < 8; b++) h1s[(w * 8 + b) * 32 + lc] = f2sum(acc[b]);
        __syncthreads();
        {
            float s = b1s[lc];
            #pragma unroll
            for (int r = 0; r < 8; r++) s += h1s[(r * 8 + w) * 32 + lc];
            float hn = tanhf(s);
            int gi = (b0 + w) * DM + c0 + lc;
            g_h1[p * TB * DM + gi]    = hn;
            g_h1all[t * TB * DM + gi] = hn;
        }
        gsync(bb, &tgt);    // h1_new visible; WAR-safe for next step
    }
}

// ---------------------------------------------------------------------------
// k_out: out[b][t][:] = h1all[t][b][:] @ Wout + bout. grid 512, 256 thr.
// Wp[k2][j] pairs (128KB) + k-chunked h staging (32KB). FFMA2 inner loop.
// ---------------------------------------------------------------------------
__global__ void __launch_bounds__(256, 1)
k_out(const float* __restrict__ Wout, const float* __restrict__ bout,
      float* __restrict__ out)
{
    extern __shared__ float sm[];
    float2* Wp = (float2*)sm;            // [256 k2][64 j]
    float*  hs = sm + 2 * 256 * DOUT;    // [64][128] k-chunk

    const int t = blockIdx.x, tid = threadIdx.x;
    for (int i = tid; i < 256 * DOUT; i += 256) {
        int k2 = i >> 6, j = i & 63;
        Wp[i] = make_float2(Wout[(2 * k2) * DOUT + j], Wout[(2 * k2 + 1) * DOUT + j]);
    }

    const int j  = tid & 63;
    const int bq = tid >> 6;             // batches [16bq, 16bq+16)
    u64 acc[2][8];
    #pragma unroll
    for (int g = 0; g < 2; g++)
        #pragma unroll
        for (int b = 0; b < 8; b++) acc[g][b] = 0ULL;

    for (int kc = 0; kc < 4; kc++) {
        __syncthreads();
        for (int idx = tid; idx < TB * 128; idx += 256) {
            int b = idx >> 7, kk = idx & 127;
            hs[idx] = g_h1all[(t * TB + b) * DM + kc * 128 + kk];
        }
        __syncthreads();
        #pragma unroll 4
        for (int k2l = 0; k2l < 64; k2l++) {
            u64 w2 = *(const u64*)&Wp[(kc * 64 + k2l) * DOUT + j];
            #pragma unroll
            for (int g = 0; g < 2; g++)
                #pragma unroll
                for (int b = 0; b < 8; b++) {
                    u64 h = *(const u64*)&hs[(bq * 16 + g * 8 + b) * 128 + 2 * k2l];
                    acc[g][b] = ffma2(h, w2, acc[g][b]);
                }
        }
    }
    float bj = bout[j];
    #pragma unroll
    for (int g = 0; g < 2; g++)
        #pragma unroll
        for (int b = 0; b < 8; b++) {
            int bg = bq * 16 + g * 8 + b;
            out[(bg * TT + t) * DOUT + j] = f2sum(acc[g][b]) + bj;
        }
}

// ---------------------------------------------------------------------------
extern "C" void kernel_launch(void* const* d_in, const int* in_sizes, int n_in,
                              void* d_out, int out_size)
{
    const float* data = (const float*)d_in[0];
    const float* Wih0 = (const float*)d_in[1];
    const float* bih0 = (const float*)d_in[2];
    const float* Whh0 = (const float*)d_in[3];
    const float* bhh0 = (const float*)d_in[4];
    const float* Wih1 = (const float*)d_in[5];
    const float* bih1 = (const float*)d_in[6];
    const float* Whh1 = (const float*)d_in[7];
    const float* bhh1 = (const float*)d_in[8];
    const float* Wout = (const float*)d_in[9];
    const float* bout = (const float*)d_in[10];
    float* out = (float*)d_out;

    cudaFuncSetAttribute(k_pre, cudaFuncAttributeMaxDynamicSharedMemorySize, 149504);
    cudaFuncSetAttribute(k_seq, cudaFuncAttributeMaxDynamicSharedMemorySize, 229504);
    cudaFuncSetAttribute(k_out, cudaFuncAttributeMaxDynamicSharedMemorySize, 163840);

    k_pre<<<TT, 256, 149504>>>(data, Wih0, bih0, bhh0);
    k_seq<<<GB, 256, 229504>>>(Whh0, Wih1, bih1, Whh1, bhh1);
    k_out<<<TT, 256, 163840>>>(Wout, bout, out);
}

// round 7
// speedup vs baseline: 1.3679x; 1.3679x over previous
#include <cuda_runtime.h>

#define TB   64      // batch
#define TT   512     // timesteps
#define DIN  64
#define DM   512     // d_model
#define DOUT 64
#define NCB  16      // column blocks
#define NC   32      // cols per CTA
#define NBB  8       // batch blocks
#define NB   8       // batches per CTA
#define GB   128     // persistent grid

typedef unsigned long long u64;

// ---- device scratch (allocation-free) --------------------------------------
__device__ float g_pre0 [TT * TB * DM];   // [t][b][j]
__device__ float g_h1all[TT * TB * DM];   // [t][b][j]
__device__ float g_h0   [2 * TB * DM];    // ping-pong h0
__device__ float g_h1   [2 * TB * DM];    // ping-pong h1
__device__ unsigned int g_bars[NBB];      // monotonic per-batchblock counters

// packed fp32x2 FMA — kept ONLY in k_pre (measured win there; regression in k_seq)
__device__ __forceinline__ u64 ffma2(u64 a, u64 b, u64 c) {
    u64 d;
    asm("fma.rn.f32x2 %0, %1, %2, %3;" : "=l"(d) : "l"(a), "l"(b), "l"(c));
    return d;
}
__device__ __forceinline__ float f2sum(u64 v) {
    float x, y;
    asm("mov.b64 {%0,%1}, %2;" : "=f"(x), "=f"(y) : "l"(v));
    return x + y;
}

// ---------------------------------------------------------------------------
// k_pre (unchanged from measured-160us version): pre0 = x@Wih0 + bih0 + bhh0.
// Also resets barrier counters and zeros parity-1 hidden state.
// ---------------------------------------------------------------------------
__global__ void __launch_bounds__(256, 1)
k_pre(const float* __restrict__ data, const float* __restrict__ Wih0,
      const float* __restrict__ bih0, const float* __restrict__ bhh0)
{
    extern __shared__ float sm[];
    float*  xs = sm;                          // [64][64]
    float2* Wp = (float2*)(sm + TB * DIN);    // [32 k2][512 j]
    float*  bs = sm + TB * DIN + 2 * 32 * DM; // [512]

    const int t = blockIdx.x, tid = threadIdx.x;
    if (t == 0 && tid < NBB) g_bars[tid] = 0u;
    if (t < 128) {
        int i = t * 256 + tid;
        g_h0[TB * DM + i] = 0.0f;
        g_h1[TB * DM + i] = 0.0f;
    }

    for (int i = tid; i < TB * DIN; i += 256) {
        int b = i >> 6, k = i & 63;
        xs[b * DIN + k] = data[(b * TT + t) * DIN + k];
    }
    for (int i = tid; i < 32 * DM; i += 256) {
        int k2 = i >> 9, j = i & 511;
        Wp[i] = make_float2(Wih0[(2 * k2) * DM + j], Wih0[(2 * k2 + 1) * DM + j]);
    }
    for (int i = tid; i < DM; i += 256) bs[i] = bih0[i] + bhh0[i];
    __syncthreads();

    const int j0 = tid;
    for (int g = 0; g < 8; g++) {
        u64 acc[2][8];
        #pragma unroll
        for (int c = 0; c < 2; c++)
            #pragma unroll
            for (int b = 0; b < 8; b++) acc[c][b] = 0ULL;
        #pragma unroll 8
        for (int k2 = 0; k2 < 32; k2++) {
            u64 w0 = *(const u64*)&Wp[k2 * DM + j0];
            u64 w1 = *(const u64*)&Wp[k2 * DM + j0 + 256];
            #pragma unroll
            for (int b = 0; b < 8; b++) {
                u64 h = *(const u64*)&xs[(g * 8 + b) * DIN + 2 * k2];
                acc[0][b] = ffma2(h, w0, acc[0][b]);
                acc[1][b] = ffma2(h, w1, acc[1][b]);
            }
        }
        #pragma unroll
        for (int b = 0; b < 8; b++) {
            int bg = g * 8 + b;
            g_pre0[(t * TB + bg) * DM + j0]       = f2sum(acc[0][b]) + bs[j0];
            g_pre0[(t * TB + bg) * DM + j0 + 256] = f2sum(acc[1][b]) + bs[j0 + 256];
        }
    }
}

// ---------------------------------------------------------------------------
// split arrive / wait (per-batchblock, 16 CTAs, monotonic counter)
// ---------------------------------------------------------------------------
__device__ __forceinline__ void arrive(int bb)
{
    __threadfence();                  // release this thread's global stores
    __syncthreads();                  // whole CTA fenced before counting
    if (threadIdx.x == 0) atomicAdd(&g_bars[bb], 1u);
}
__device__ __forceinline__ void waitcnt(int bb, unsigned int tgt)
{
    if (threadIdx.x == 0) {
        while (*(volatile unsigned int*)&g_bars[bb] < tgt) { }
        __threadfence();
    }
    __syncthreads();
}

// copy 4096 floats (8 batch rows of h) global -> smem, L2-coherent
__device__ __forceinline__ void stage(float* dst, const float* src, int tid)
{
    const float4* s = (const float4*)src;
    float4*       d = (float4*)dst;
    #pragma unroll
    for (int j = 0; j < 4; j++) d[tid + 256 * j] = __ldcg(&s[tid + 256 * j]);
}

// warp-slice GEMM: acc[b] += sum_{k in warp slice} h[b][k] * W[k][lane-col]
__device__ __forceinline__ void gemm_slice(const float4* __restrict__ Wv,
                                           const float* __restrict__ hbuf,
                                           int kg0, int lc, float acc[8])
{
    #pragma unroll 4
    for (int kg = kg0; kg < kg0 + 16; kg++) {
        float4 wv = Wv[kg * 32 + lc];
        #pragma unroll
        for (int b = 0; b < 8; b++) {
            float4 h = *(const float4*)&hbuf[b * DM + kg * 4]; // broadcast
            acc[b] = fmaf(h.x, wv.x, acc[b]);
            acc[b] = fmaf(h.y, wv.y, acc[b]);
            acc[b] = fmaf(h.z, wv.z, acc[b]);
            acc[b] = fmaf(h.w, wv.w, acc[b]);
        }
    }
}

// ---------------------------------------------------------------------------
// k_seq: 512 steps, 128 persistent CTAs x 256 thr, smem 229504 B.
// Software-pipelined: both barrier waits hidden behind 2K-cycle GEMMs.
//   per iter t:
//     partial = h1_prev@Whh1            (hides wait A_t)
//     wait A_t; stage h0s <- h0_t
//     phase2: partial += h0_t@Wih1 -> h1_t ; arrive B_t
//     phase1_{t+1}: h0_t@Whh0 -> h0_{t+1} ; arrive A_{t+1}   (hides wait B_t)
//     wait B_t; stage h1s <- h1_t
// Reduction scratch lives in the dead h-buffer of each phase (no extra smem).
// ---------------------------------------------------------------------------
__global__ void __launch_bounds__(256, 1)
k_seq(const float* __restrict__ Whh0, const float* __restrict__ Wih1,
      const float* __restrict__ bih1, const float* __restrict__ Whh1,
      const float* __restrict__ bhh1)
{
    extern __shared__ float sm[];
    float4* W0  = (float4*)sm;          // [4096] float4 (Whh0 slice)
    float4* W1  = W0 + 4096;            // Wih1 slice
    float4* W2  = W1 + 4096;            // Whh1 slice
    float*  h0s = sm + 3 * 16384;       // [8][512]
    float*  h1s = h0s + NB * DM;        // [8][512]
    float*  b1s = h1s + NB * DM;        // [32]

    const int tid = threadIdx.x;
    const int cb  = blockIdx.x & (NCB - 1);
    const int bb  = blockIdx.x >> 4;
    const int c0  = cb * NC, b0 = bb * NB;

    for (int idx = tid; idx < 4096; idx += 256) {
        int kg = idx >> 5, c = idx & 31;
        int kb = kg * 4, cg = c0 + c;
        float4 v;
        v.x = Whh0[(kb+0)*DM+cg]; v.y = Whh0[(kb+1)*DM+cg];
        v.z = Whh0[(kb+2)*DM+cg]; v.w = Whh0[(kb+3)*DM+cg];
        W0[idx] = v;
        v.x = Wih1[(kb+0)*DM+cg]; v.y = Wih1[(kb+1)*DM+cg];
        v.z = Wih1[(kb+2)*DM+cg]; v.w = Wih1[(kb+3)*DM+cg];
        W1[idx] = v;
        v.x = Whh1[(kb+0)*DM+cg]; v.y = Whh1[(kb+1)*DM+cg];
        v.z = Whh1[(kb+2)*DM+cg]; v.w = Whh1[(kb+3)*DM+cg];
        W2[idx] = v;
    }
    if (tid < NC) b1s[tid] = bih1[c0 + tid] + bhh1[c0 + tid];

    // prologue: prime h buffers with zeros (parity-1, zeroed by k_pre)
    stage(h0s, g_h0 + TB * DM + b0 * DM, tid);
    stage(h1s, g_h1 + TB * DM + b0 * DM, tid);
    __syncthreads();

    const int w   = tid >> 5;   // warp = k-slice; also batch id in reduction
    const int lc  = tid & 31;
    const int kg0 = w * 16;
    float acc[8];

    // ---- prologue: phase1_0 (h0s = zeros) ----
    {
        #pragma unroll
        for (int b = 0; b < 8; b++) acc[b] = 0.0f;
        gemm_slice(W0, h0s, kg0, lc, acc);
        __syncthreads();
        #pragma unroll
        for (int b = 0; b < 8; b++) h0s[(w * 8 + b) * 32 + lc] = acc[b];
        __syncthreads();
        float s = __ldg(&g_pre0[(b0 + w) * DM + c0 + lc]);   // t=0
        #pragma unroll
        for (int r = 0; r < 8; r++) s += h0s[(r * 8 + w) * 32 + lc];
        g_h0[(b0 + w) * DM + c0 + lc] = tanhf(s);            // parity 0
        arrive(bb);                                          // A_0
    }

    for (int t = 0; t < TT; t++) {
        const int p = t & 1;

        // partial = h1_prev @ Whh1   (hides wait A_t)
        #pragma unroll
        for (int b = 0; b < 8; b++) acc[b] = 0.0f;
        gemm_slice(W2, h1s, kg0, lc, acc);

        waitcnt(bb, (unsigned)(2 * t + 1) * NCB);            // A_t
        stage(h0s, g_h0 + p * TB * DM + b0 * DM, tid);       // h0_t
        __syncthreads();

        // phase2: partial += h0_t @ Wih1 -> h1_t
        gemm_slice(W1, h0s, kg0, lc, acc);
        __syncthreads();                 // all warps done reading h1s
        #pragma unroll
        for (int b = 0; b < 8; b++) h1s[(w * 8 + b) * 32 + lc] = acc[b];
        __syncthreads();
        {
            float s = b1s[lc];
            #pragma unroll
            for (int r = 0; r < 8; r++) s += h1s[(r * 8 + w) * 32 + lc];
            float hn = tanhf(s);
            int gi = (b0 + w) * DM + c0 + lc;
            g_h1[p * TB * DM + gi]    = hn;
            g_h1all[t * TB * DM + gi] = hn;
        }
        arrive(bb);                                          // B_t

        // phase1_{t+1}: h0_t @ Whh0 -> h0_{t+1}   (hides wait B_t)
        if (t + 1 < TT) {
            float pre = __ldg(&g_pre0[((t + 1) * TB + b0 + w) * DM + c0 + lc]);
            #pragma unroll
            for (int b = 0; b < 8; b++) acc[b] = 0.0f;
            gemm_slice(W0, h0s, kg0, lc, acc);
            __syncthreads();             // all warps done reading h0s
            #pragma unroll
            for (int b = 0; b < 8; b++) h0s[(w * 8 + b) * 32 + lc] = acc[b];
            __syncthreads();
            float s = pre;
            #pragma unroll
            for (int r = 0; r < 8; r++) s += h0s[(r * 8 + w) * 32 + lc];
            g_h0[(p ^ 1) * TB * DM + (b0 + w) * DM + c0 + lc] = tanhf(s);
            arrive(bb);                                      // A_{t+1}
        }

        waitcnt(bb, (unsigned)(2 * t + 2) * NCB);            // B_t (near-free)
        stage(h1s, g_h1 + p * TB * DM + b0 * DM, tid);       // h1_t
        __syncthreads();
    }
}

// ---------------------------------------------------------------------------
// k_out (round-1 proven version): out[b][t][:] = h1all[t][b][:] @ Wout + bout
// ---------------------------------------------------------------------------
__global__ void __launch_bounds__(256, 1)
k_out(const float* __restrict__ Wout, const float* __restrict__ bout,
      float* __restrict__ out)
{
    extern __shared__ float sm[];
    float* Ws = sm;                 // [512][64]
    float* hs = Ws + DM * DOUT;     // [64][128] k-chunk

    const int t = blockIdx.x, tid = threadIdx.x;
    for (int i = tid; i < DM * DOUT; i += 256) Ws[i] = Wout[i];

    const int j  = tid & 63;
    const int bq = tid >> 6;
    float acc[16];
    #pragma unroll
    for (int i = 0; i < 16; i++) acc[i] = 0.0f;

    for (int kc = 0; kc < 4; kc++) {
        __syncthreads();
        for (int idx = tid; idx < TB * 128; idx += 256) {
            int b = idx >> 7, kk = idx & 127;
            hs[idx] = g_h1all[(t * TB + b) * DM + kc * 128 + kk];
        }
        __syncthreads();
        for (int kk = 0; kk < 128; kk++) {
            float wv = Ws[(kc * 128 + kk) * DOUT + j];
            #pragma unroll
            for (int i = 0; i < 16; i++)
                acc[i] = fmaf(hs[(bq * 16 + i) * 128 + kk], wv, acc[i]);
        }
    }
    float bj = bout[j];
    #pragma unroll
    for (int i = 0; i < 16; i++) {
        int b = bq * 16 + i;
        out[(b * TT + t) * DOUT + j] = acc[i] + bj;
    }
}

// ---------------------------------------------------------------------------
extern "C" void kernel_launch(void* const* d_in, const int* in_sizes, int n_in,
                              void* d_out, int out_size)
{
    const float* data = (const float*)d_in[0];
    const float* Wih0 = (const float*)d_in[1];
    const float* bih0 = (const float*)d_in[2];
    const float* Whh0 = (const float*)d_in[3];
    const float* bhh0 = (const float*)d_in[4];
    const float* Wih1 = (const float*)d_in[5];
    const float* bih1 = (const float*)d_in[6];
    const float* Whh1 = (const float*)d_in[7];
    const float* bhh1 = (const float*)d_in[8];
    const float* Wout = (const float*)d_in[9];
    const float* bout = (const float*)d_in[10];
    float* out = (float*)d_out;

    cudaFuncSetAttribute(k_pre, cudaFuncAttributeMaxDynamicSharedMemorySize, 149504);
    cudaFuncSetAttribute(k_seq, cudaFuncAttributeMaxDynamicSharedMemorySize, 229504);
    cudaFuncSetAttribute(k_out, cudaFuncAttributeMaxDynamicSharedMemorySize, 163840);

    k_pre<<<TT, 256, 149504>>>(data, Wih0, bih0, bhh0);
    k_seq<<<GB, 256, 229504>>>(Whh0, Wih1, bih1, Whh1, bhh1);
    k_out<<<TT, 256, 163840>>>(Wout, bout, out);
}